// round 5
// baseline (speedup 1.0000x reference)
#include <cuda_runtime.h>

#define BN 256
#define CN 1024
#define HW 169        // 13*13
#define SPLIT 5       // -> 1280 one-warp blocks
#define Z_CONST 17.079468445347132f   // 2*pi*e
#define EPS_CONST 1e-6f

// Per-(b, split, moment, channel) partials: S, Sx, Sy, Sr=Σ(wx^2+wy^2)f.
// 256*5*4*1024 floats = 21 MB.
__device__ float g_part[BN * SPLIT * 4 * CN];

// packed fp32x2 ops (ptxas won't auto-fuse; PTX-only)
#define PACK2(d, lo, hi)   asm("mov.b64 %0, {%1, %2};" : "=l"(d) : "f"(lo), "f"(hi))
#define UNPACK2(lo, hi, a) asm("mov.b64 {%0, %1}, %2;" : "=f"(lo), "=f"(hi) : "l"(a))
#define ADD2(d, a, b)      asm("add.rn.f32x2 %0, %1, %2;" : "=l"(d) : "l"(a), "l"(b))
#define FMA2(d, a, b, c)   asm("fma.rn.f32x2 %0, %1, %2, %3;" : "=l"(d) : "l"(a), "l"(b), "l"(c))

// ---------------------------------------------------------------------------
// Kernel 1: one warp per (batch, position-chunk). Lane owns 8x4 channels
// (chunks of 128). Softmax denom = in-lane packed tree + 5 shfl. No smem,
// no barriers. Accumulation in packed f32x2.
// ---------------------------------------------------------------------------
__global__ __launch_bounds__(32) void accum_kernel(const float* __restrict__ x,
                                                   float* __restrict__ out) {
    if (blockIdx.x == 0 && threadIdx.x == 0) out[0] = 0.0f;

    const int b    = blockIdx.x / SPLIT;
    const int sp   = blockIdx.x - b * SPLIT;
    const int p0   = (sp * HW) / SPLIT;
    const int p1   = ((sp + 1) * HW) / SPLIT;
    const int lane = threadIdx.x;

    const float4* __restrict__ xb = (const float4*)(x + (size_t)b * HW * CN);

    unsigned long long S[16], Sx[16], Sy[16], Sr[16];
#pragma unroll
    for (int i = 0; i < 16; ++i) { S[i] = 0ull; Sx[i] = 0ull; Sy[i] = 0ull; Sr[i] = 0ull; }

    // incremental spatial weights
    const int h0 = p0 / 13;
    float wx = (float)(h0 + 1);
    float wy = (float)(p0 - h0 * 13 + 1);

    // prologue: load position p0 (8 float4 per lane = 32 channels)
    float4 cur[8];
#pragma unroll
    for (int u = 0; u < 8; ++u)
        cur[u] = __ldcs(xb + (size_t)p0 * 256 + u * 32 + lane);

    for (int p = p0; p < p1; ++p) {
        // exps -> packed pairs (frees cur for the prefetch)
        unsigned long long e[16];
#pragma unroll
        for (int u = 0; u < 8; ++u) {
            float a = __expf(cur[u].x), bb = __expf(cur[u].y);
            float c = __expf(cur[u].z), d  = __expf(cur[u].w);
            PACK2(e[2 * u],     a, bb);
            PACK2(e[2 * u + 1], c, d);
        }

        // prefetch next position (covers DRAM latency across this body)
        if (p + 1 < p1) {
#pragma unroll
            for (int u = 0; u < 8; ++u)
                cur[u] = __ldcs(xb + (size_t)(p + 1) * 256 + u * 32 + lane);
        }

        // in-lane packed reduction tree (16 -> 1)
        unsigned long long t[8];
#pragma unroll
        for (int i = 0; i < 8; ++i) ADD2(t[i], e[2 * i], e[2 * i + 1]);
        ADD2(t[0], t[0], t[1]); ADD2(t[2], t[2], t[3]);
        ADD2(t[4], t[4], t[5]); ADD2(t[6], t[6], t[7]);
        ADD2(t[0], t[0], t[2]); ADD2(t[4], t[4], t[6]);
        ADD2(t[0], t[0], t[4]);
        float lo, hi; UNPACK2(lo, hi, t[0]);
        float s = lo + hi;
#pragma unroll
        for (int m = 16; m > 0; m >>= 1)
            s += __shfl_xor_sync(0xffffffffu, s, m);

        float inv = __fdividef(1.0f, s);
        float w1  = inv * wx;
        float w2  = inv * wy;
        float wr  = fmaf(wx, wx, wy * wy) * inv;
        unsigned long long inv2, w12, w22, wr2;
        PACK2(inv2, inv, inv); PACK2(w12, w1, w1);
        PACK2(w22, w2, w2);    PACK2(wr2, wr, wr);

        // 64 packed FMAs: 4 moments x 16 channel-pairs
#pragma unroll
        for (int i = 0; i < 16; ++i) {
            FMA2(S[i],  inv2, e[i], S[i]);
            FMA2(Sx[i], w12,  e[i], Sx[i]);
            FMA2(Sy[i], w22,  e[i], Sy[i]);
            FMA2(Sr[i], wr2,  e[i], Sr[i]);
        }

        wy += 1.0f;
        if (wy > 13.0f) { wy = 1.0f; wx += 1.0f; }
    }

    // store partials: [B][SPLIT][4][CN], 512B coalesced per (moment, chunk)
    float* gp = g_part + (size_t)(b * SPLIT + sp) * 4 * CN;
#pragma unroll
    for (int u = 0; u < 8; ++u) {
        const int off = u * 128 + lane * 4;
        *(ulonglong2*)(gp + 0 * CN + off) = make_ulonglong2(S[2 * u],  S[2 * u + 1]);
        *(ulonglong2*)(gp + 1 * CN + off) = make_ulonglong2(Sx[2 * u], Sx[2 * u + 1]);
        *(ulonglong2*)(gp + 2 * CN + off) = make_ulonglong2(Sy[2 * u], Sy[2 * u + 1]);
        *(ulonglong2*)(gp + 3 * CN + off) = make_ulonglong2(Sr[2 * u], Sr[2 * u + 1]);
    }
}

// ---------------------------------------------------------------------------
// Kernel 2: sum splits, per-(b,c) det, block reduce, atomicAdd scalar.
// grid = 1024 blocks x 256 thr; thread owns ONE channel (coalesced loads).
// ---------------------------------------------------------------------------
__global__ __launch_bounds__(256) void final_kernel(float* __restrict__ out) {
    const int bb  = blockIdx.x;          // 0..1023
    const int b   = bb >> 2;
    const int c   = ((bb & 3) << 8) + threadIdx.x;
    const int tid = threadIdx.x;

    float m0 = 0.f, m1 = 0.f, m2 = 0.f, m3 = 0.f;
#pragma unroll
    for (int s = 0; s < SPLIT; ++s) {
        const float* gs = g_part + (size_t)(b * SPLIT + s) * 4 * CN;
        m0 += gs[0 * CN + c];
        m1 += gs[1 * CN + c];
        m2 += gs[2 * CN + c];
        m3 += gs[3 * CN + c];
    }

    float s     = m0 + EPS_CONST;
    float inv_s = 1.0f / s;
    float mx    = m1 * inv_s;
    float my    = m2 * inv_s;
    float num   = m3 - 2.0f * (mx * m1 + my * m2) + (mx * mx + my * my) * m0;
    float d     = num * inv_s * (1.0f / 169.0f);
    float acc   = d * d * Z_CONST;

#pragma unroll
    for (int msk = 16; msk > 0; msk >>= 1)
        acc += __shfl_xor_sync(0xffffffffu, acc, msk);

    __shared__ float wsum[8];
    if ((tid & 31) == 0) wsum[tid >> 5] = acc;
    __syncthreads();
    if (tid == 0) {
        float t = ((wsum[0] + wsum[1]) + (wsum[2] + wsum[3]))
                + ((wsum[4] + wsum[5]) + (wsum[6] + wsum[7]));
        atomicAdd(out, t * (1.0f / (float)(BN * CN)));
    }
}

// ---------------------------------------------------------------------------
extern "C" void kernel_launch(void* const* d_in, const int* in_sizes, int n_in,
                              void* d_out, int out_size) {
    const float* x = (const float*)d_in[0];
    float* out = (float*)d_out;

    accum_kernel<<<BN * SPLIT, 32>>>(x, out);
    final_kernel<<<1024, 256>>>(out);
}